// round 11
// baseline (speedup 1.0000x reference)
#include <cuda_runtime.h>
#include <cuda_fp16.h>
#include <cstdint>

// Problem constants
#define BATCH 64
#define SEQ   197
#define EDIM  768
#define NH    12
#define HD    64
#define MROWS (BATCH * SEQ)          // 12608
#define PERB  (SEQ * EDIM)
#define PERH  (SEQ * HD)

// fp16 operands. A-side (x, Q, AO) split hi+lo (~22 mantissa bits combined);
// B-side (W, K, V) rounded once to fp16.
__device__ __align__(16) __half g_x_hi[MROWS * EDIM];
__device__ __align__(16) __half g_x_lo[MROWS * EDIM];
__device__ __align__(16) __half g_w[4][EDIM * EDIM];     // q,k,v,p (single)
__device__ __align__(16) __half g_q_hi[MROWS * EDIM];
__device__ __align__(16) __half g_q_lo[MROWS * EDIM];
__device__ __align__(16) __half g_k[MROWS * EDIM];       // single
__device__ __align__(16) __half g_v[MROWS * EDIM];       // single
__device__ __align__(16) __half g_ao_hi[MROWS * EDIM];
__device__ __align__(16) __half g_ao_lo[MROWS * EDIM];

// ---------------------------------------------------------------------------
// mma / ldmatrix / cp.async helpers
// ---------------------------------------------------------------------------
__device__ __forceinline__ void mma_f16(
    float& d0, float& d1, float& d2, float& d3,
    unsigned a0, unsigned a1, unsigned a2, unsigned a3,
    unsigned b0, unsigned b1)
{
    asm volatile(
        "mma.sync.aligned.m16n8k16.row.col.f32.f16.f16.f32 "
        "{%0,%1,%2,%3}, {%4,%5,%6,%7}, {%8,%9}, {%0,%1,%2,%3};\n"
        : "+f"(d0), "+f"(d1), "+f"(d2), "+f"(d3)
        : "r"(a0), "r"(a1), "r"(a2), "r"(a3), "r"(b0), "r"(b1));
}

__device__ __forceinline__ void ldsm4(unsigned& r0, unsigned& r1,
                                      unsigned& r2, unsigned& r3, uint32_t addr)
{
    asm volatile("ldmatrix.sync.aligned.m8n8.x4.shared.b16 {%0,%1,%2,%3}, [%4];"
                 : "=r"(r0), "=r"(r1), "=r"(r2), "=r"(r3) : "r"(addr));
}

__device__ __forceinline__ void ldsm2(unsigned& r0, unsigned& r1, uint32_t addr)
{
    asm volatile("ldmatrix.sync.aligned.m8n8.x2.shared.b16 {%0,%1}, [%2];"
                 : "=r"(r0), "=r"(r1) : "r"(addr));
}

__device__ __forceinline__ void cp_async16(uint32_t dst, const void* src, int srcSz)
{
    asm volatile("cp.async.cg.shared.global [%0], [%1], 16, %2;"
                 :: "r"(dst), "l"(src), "r"(srcSz) : "memory");
}
#define CP_COMMIT() asm volatile("cp.async.commit_group;" ::: "memory")
#define CP_WAIT0()  asm volatile("cp.async.wait_group 0;" ::: "memory")

__device__ __forceinline__ unsigned prmt(unsigned a, unsigned b, unsigned sel) {
    unsigned r;
    asm("prmt.b32 %0, %1, %2, %3;" : "=r"(r) : "r"(a), "r"(b), "r"(sel));
    return r;
}

__device__ __forceinline__ unsigned pack_h2(float a, float b) {
    __half2 h = __floats2half2_rn(a, b);
    return *reinterpret_cast<unsigned*>(&h);
}

// ---------------------------------------------------------------------------
// Conversion kernels
// ---------------------------------------------------------------------------
__global__ void split_x_kernel(const float* __restrict__ x, int n4)
{
    int i = blockIdx.x * blockDim.x + threadIdx.x;
    if (i >= n4) return;
    float4 v = ((const float4*)x)[i];
    float h0 = __half2float(__float2half_rn(v.x));
    float h1 = __half2float(__float2half_rn(v.y));
    float h2 = __half2float(__float2half_rn(v.z));
    float h3 = __half2float(__float2half_rn(v.w));
    uint2 ph, pl;
    ph.x = pack_h2(v.x, v.y);
    ph.y = pack_h2(v.z, v.w);
    pl.x = pack_h2(v.x - h0, v.y - h1);
    pl.y = pack_h2(v.z - h2, v.w - h3);
    ((uint2*)g_x_hi)[i] = ph;
    ((uint2*)g_x_lo)[i] = pl;
}

__global__ void conv_w_kernel(const float* __restrict__ Wq,
                              const float* __restrict__ Wk,
                              const float* __restrict__ Wv,
                              const float* __restrict__ Wp, int n4)
{
    const float* src;
    const int z = blockIdx.z;
    if (z == 0) src = Wq; else if (z == 1) src = Wk;
    else if (z == 2) src = Wv; else src = Wp;
    int i = blockIdx.x * blockDim.x + threadIdx.x;
    if (i >= n4) return;
    float4 v = ((const float4*)src)[i];
    uint2 p;
    p.x = pack_h2(v.x, v.y);
    p.y = pack_h2(v.z, v.w);
    ((uint2*)g_w[z])[i] = p;
}

// ---------------------------------------------------------------------------
// fp16-2x NT GEMM: C[M,N] = (Ahi+Alo)[M,K] @ B[N,K]^T + bias
// BM=BN=128, BK=32, warp tile 64x32, ldmatrix + cp.async double-buffered.
// OUT_MODE: 0 = fp32 C; 1 = split f16 hi/lo; 2 = single f16.
// ---------------------------------------------------------------------------
#define RS 20                       // uint stride per smem row
#define ST_UINTS (128 * RS)
#define GEMM_SMEM_BYTES (6 * ST_UINTS * 4)    // 2 stages x 3 tiles = 61440 B

template <int OUT_MODE>
__device__ __forceinline__ void gemm_f16_body(
    const __half* __restrict__ Ahi, const __half* __restrict__ Alo,
    const __half* __restrict__ B,
    const float* __restrict__ bias,
    float* __restrict__ C,
    __half* __restrict__ Chi, __half* __restrict__ Clo)
{
    extern __shared__ unsigned smem_u[];

    const int tid  = threadIdx.x;
    const int warp = tid >> 5;
    const int lane = tid & 31;
    const int g    = lane >> 2;
    const int c    = lane & 3;
    const int warpM = warp & 1;
    const int warpN = warp >> 1;

    const int bm = blockIdx.y * 128;
    const int bn = blockIdx.x * 128;

    const int ldRow = tid >> 1;
    const int half_ = tid & 1;
    const int aRow  = bm + ldRow;
    const bool aValid = (aRow < MROWS);
    const int aSz = aValid ? 16 : 0;
    const size_t aOff = (size_t)(aValid ? aRow : 0) * EDIM + half_ * 16;
    const size_t bOff = (size_t)(bn + ldRow) * EDIM + half_ * 16;
    const int sBase = ldRow * RS + half_ * 8;

    const uint32_t smBase = (uint32_t)__cvta_generic_to_shared(smem_u);
    const int aLd = ((lane & 7) + 8 * ((lane >> 3) & 1)) * RS + 4 * (lane >> 4);
    const int bLd = ((lane & 7) + 8 * (lane >> 4)) * RS + 4 * ((lane >> 3) & 1);

    float acc[4][4][4];
    #pragma unroll
    for (int mt = 0; mt < 4; mt++)
        #pragma unroll
        for (int nt = 0; nt < 4; nt++)
            #pragma unroll
            for (int r = 0; r < 4; r++)
                acc[mt][nt][r] = 0.0f;

    auto issue = [&](int ch, int stage) {
        const size_t k0 = (size_t)ch * 32;
        const uint32_t st = smBase + (uint32_t)(stage * 3 * ST_UINTS) * 4;
        #pragma unroll
        for (int u = 0; u < 2; u++) {
            cp_async16(st + (uint32_t)(sBase + u * 4) * 4,                Ahi + aOff + k0 + u * 8, aSz);
            cp_async16(st + (uint32_t)(ST_UINTS + sBase + u * 4) * 4,     Alo + aOff + k0 + u * 8, aSz);
            cp_async16(st + (uint32_t)(2 * ST_UINTS + sBase + u * 4) * 4, B + bOff + k0 + u * 8, 16);
        }
        CP_COMMIT();
    };

    issue(0, 0);

    const int nCh = EDIM / 32;   // 24
    for (int ch = 0; ch < nCh; ch++) {
        const int stage = ch & 1;
        CP_WAIT0();
        __syncthreads();
        if (ch + 1 < nCh) issue(ch + 1, stage ^ 1);

        const uint32_t sAh = smBase + (uint32_t)(stage * 3 * ST_UINTS) * 4;
        const uint32_t sAl = sAh + ST_UINTS * 4;
        const uint32_t sB  = sAl + ST_UINTS * 4;

        #pragma unroll
        for (int ks = 0; ks < 2; ks++) {
            const int kk = ks * 8;
            unsigned ah[4][4], al[4][4], bf[4][2];
            #pragma unroll
            for (int mt = 0; mt < 4; mt++) {
                const uint32_t ao = (uint32_t)(((warpM * 64 + mt * 16) * RS + kk + aLd) * 4);
                ldsm4(ah[mt][0], ah[mt][1], ah[mt][2], ah[mt][3], sAh + ao);
                ldsm4(al[mt][0], al[mt][1], al[mt][2], al[mt][3], sAl + ao);
            }
            #pragma unroll
            for (int p = 0; p < 2; p++) {
                const uint32_t bo = (uint32_t)(((warpN * 32 + p * 16) * RS + kk + bLd) * 4);
                ldsm4(bf[2 * p][0], bf[2 * p][1], bf[2 * p + 1][0], bf[2 * p + 1][1], sB + bo);
            }
            #pragma unroll
            for (int mt = 0; mt < 4; mt++)
                #pragma unroll
                for (int nt = 0; nt < 4; nt++) {
                    float* d = acc[mt][nt];
                    mma_f16(d[0], d[1], d[2], d[3],
                            ah[mt][0], ah[mt][1], ah[mt][2], ah[mt][3],
                            bf[nt][0], bf[nt][1]);
                    mma_f16(d[0], d[1], d[2], d[3],
                            al[mt][0], al[mt][1], al[mt][2], al[mt][3],
                            bf[nt][0], bf[nt][1]);
                }
        }
        __syncthreads();
    }

    // epilogue
    #pragma unroll
    for (int mt = 0; mt < 4; mt++) {
        const int row0 = bm + warpM * 64 + mt * 16 + g;
        const int row1 = row0 + 8;
        #pragma unroll
        for (int nt = 0; nt < 4; nt++) {
            const int col = bn + warpN * 32 + nt * 8 + 2 * c;
            const float b0 = bias[col];
            const float b1 = bias[col + 1];
            float v00 = acc[mt][nt][0] + b0, v01 = acc[mt][nt][1] + b1;
            float v10 = acc[mt][nt][2] + b0, v11 = acc[mt][nt][3] + b1;
            if (OUT_MODE == 1) {
                if (row0 < MROWS) {
                    size_t ui = ((size_t)row0 * EDIM + col) >> 1;
                    float h0 = __half2float(__float2half_rn(v00));
                    float h1 = __half2float(__float2half_rn(v01));
                    ((unsigned*)Chi)[ui] = pack_h2(v00, v01);
                    ((unsigned*)Clo)[ui] = pack_h2(v00 - h0, v01 - h1);
                }
                if (row1 < MROWS) {
                    size_t ui = ((size_t)row1 * EDIM + col) >> 1;
                    float h0 = __half2float(__float2half_rn(v10));
                    float h1 = __half2float(__float2half_rn(v11));
                    ((unsigned*)Chi)[ui] = pack_h2(v10, v11);
                    ((unsigned*)Clo)[ui] = pack_h2(v10 - h0, v11 - h1);
                }
            } else if (OUT_MODE == 2) {
                if (row0 < MROWS)
                    ((unsigned*)Chi)[((size_t)row0 * EDIM + col) >> 1] = pack_h2(v00, v01);
                if (row1 < MROWS)
                    ((unsigned*)Chi)[((size_t)row1 * EDIM + col) >> 1] = pack_h2(v10, v11);
            } else {
                if (row0 < MROWS)
                    *(float2*)(C + (size_t)row0 * EDIM + col) = make_float2(v00, v01);
                if (row1 < MROWS)
                    *(float2*)(C + (size_t)row1 * EDIM + col) = make_float2(v10, v11);
            }
        }
    }
}

__global__ __launch_bounds__(256, 2) void qkv_gemm_kernel(
    const float* __restrict__ bq, const float* __restrict__ bk,
    const float* __restrict__ bv)
{
    if (blockIdx.z == 0)
        gemm_f16_body<1>(g_x_hi, g_x_lo, g_w[0], bq, nullptr, g_q_hi, g_q_lo);
    else if (blockIdx.z == 1)
        gemm_f16_body<2>(g_x_hi, g_x_lo, g_w[1], bk, nullptr, g_k, nullptr);
    else
        gemm_f16_body<2>(g_x_hi, g_x_lo, g_w[2], bv, nullptr, g_v, nullptr);
}

__global__ __launch_bounds__(256, 2) void proj_gemm_kernel(
    const float* __restrict__ bp, float* __restrict__ out)
{
    gemm_f16_body<0>(g_ao_hi, g_ao_lo, g_w[3], bp, out, nullptr, nullptr);
}

// ---------------------------------------------------------------------------
// Attention: fp16-2x mma + ldmatrix, 512 threads, 64-row stripes.
// Q split hi/lo (A-side), K single, V single (B-side). P stored UNNORMALIZED
// split hi/lo (exact); 1/(sum*sqrt(768)) applied to O at epilogue via inv[].
// ---------------------------------------------------------------------------
#define SP   224
#define KSU  36          // uint stride, K/Q rows
#define VSU  116         // uint stride, Vt rows
#define EPS  236         // word stride, E rows (fp32) / P rows (uints)
#define PLOFF 120        // Pl offset within an E/P row (uints)

#define SM_K    0
#define SM_VT   (SM_K + SP * KSU)                 // 8064
#define SM_QH   (SM_VT + 64 * VSU)                // 15488
#define SM_QL   (SM_QH + 64 * KSU)                // 17792
#define SM_INV  (SM_QL + 64 * KSU)                // 20096
#define SM_EP   (SM_INV + 64)                     // 20160
#define ATTN_SMEM_WORDS (SM_EP + 64 * EPS)        // 35264
#define ATTN_SMEM_BYTES (ATTN_SMEM_WORDS * 4)     // 141056

__global__ __launch_bounds__(512, 1) void attn_kernel()
{
    extern __shared__ unsigned smw[];
    unsigned* Ks  = smw + SM_K;
    unsigned* Vt  = smw + SM_VT;
    unsigned* Qh  = smw + SM_QH;
    unsigned* Ql  = smw + SM_QL;
    float*    Inv = (float*)(smw + SM_INV);
    float*    E   = (float*)(smw + SM_EP);
    unsigned* Pu  = smw + SM_EP;     // P overlays E

    const int bh = blockIdx.x;
    const int b = bh / NH;
    const int h = bh % NH;
    const size_t base = (size_t)b * PERB + (size_t)h * PERH;

    const unsigned* Qgh = (const unsigned*)g_q_hi + (base >> 1);
    const unsigned* Qgl = (const unsigned*)g_q_lo + (base >> 1);
    const unsigned* Kg  = (const unsigned*)g_k + (base >> 1);
    const unsigned* Vg  = (const unsigned*)g_v + (base >> 1);
    unsigned* AOh = (unsigned*)g_ao_hi + (base >> 1);
    unsigned* AOl = (unsigned*)g_ao_lo + (base >> 1);

    const int tid  = threadIdx.x;
    const int warp = tid >> 5;
    const int lane = tid & 31;
    const int g    = lane >> 2;
    const int c    = lane & 3;
    const int wM   = warp & 3;
    const int wN   = warp >> 2;

    const uint32_t smBase = (uint32_t)__cvta_generic_to_shared(smw);
    const uint32_t sK  = smBase + SM_K  * 4;
    const uint32_t sVt = smBase + SM_VT * 4;
    const uint32_t sQh = smBase + SM_QH * 4;
    const uint32_t sQl = smBase + SM_QL * 4;
    const uint32_t sEP = smBase + SM_EP * 4;

    const int aLdK = ((lane & 7) + 8 * ((lane >> 3) & 1)) * KSU + 4 * (lane >> 4);
    const int bLdK = ((lane & 7) + 8 * (lane >> 4)) * KSU + 4 * ((lane >> 3) & 1);
    const int bLdK2 = (lane & 7) * KSU + 4 * ((lane >> 3) & 1);
    const int aLdP = ((lane & 7) + 8 * ((lane >> 3) & 1)) * EPS + 4 * (lane >> 4);
    const int bLdV = ((lane & 7) + 8 * (lane >> 4)) * VSU + 4 * ((lane >> 3) & 1);

    // zero K + Vt regions (pad rows/cols must be 0 so PV sees p*0, not NaN)
    for (int i = tid; i < (SP * KSU + 64 * VSU) / 4; i += 512)
        ((uint4*)smw)[i] = make_uint4(0u, 0u, 0u, 0u);
    __syncthreads();

    // K fill (197 rows x 8 uint4)
    for (int t = tid; t < 197 * 8; t += 512) {
        int row = t >> 3, chk = t & 7;
        *(uint4*)(Ks + row * KSU + chk * 4) = *(const uint4*)(Kg + row * 32 + chk * 4);
    }
    // Vt fill (transpose + repack along j): 99 j-pairs x 8 d-chunks
    for (int t = tid; t < 99 * 8; t += 512) {
        int j2 = t >> 3, dch = t & 7;
        int j0 = 2 * j2;
        uint4 av = *(const uint4*)(Vg + j0 * 32 + dch * 4);
        uint4 bv = make_uint4(0u, 0u, 0u, 0u);
        if (j0 + 1 < SEQ)
            bv = *(const uint4*)(Vg + (j0 + 1) * 32 + dch * 4);
        const unsigned* ap = &av.x;
        const unsigned* bp = &bv.x;
        #pragma unroll
        for (int i = 0; i < 4; i++) {
            int d = dch * 8 + 2 * i;
            Vt[(d    ) * VSU + j2] = prmt(ap[i], bp[i], 0x5410);
            Vt[(d + 1) * VSU + j2] = prmt(ap[i], bp[i], 0x7632);
        }
    }
    __syncthreads();

    for (int stripe = 0; stripe < 4; stripe++) {
        const int rbase = stripe * 64;

        // load Q stripe (64 rows x 8 chunks, hi+lo)
        {
            int row = tid >> 3, chk = tid & 7;
            int rg = rbase + row;
            uint4 vh = make_uint4(0u, 0u, 0u, 0u), vl = vh;
            if (rg < SEQ) {
                vh = *(const uint4*)(Qgh + rg * 32 + chk * 4);
                vl = *(const uint4*)(Qgl + rg * 32 + chk * 4);
            }
            *(uint4*)(Qh + row * KSU + chk * 4) = vh;
            *(uint4*)(Ql + row * KSU + chk * 4) = vl;
        }
        __syncthreads();

        // ---- E = Q_stripe @ K^T : warp tile 16 rows x 56 cols ----
        {
            float e[7][4];
            #pragma unroll
            for (int t = 0; t < 7; t++)
                #pragma unroll
                for (int r = 0; r < 4; r++) e[t][r] = 0.f;

            #pragma unroll
            for (int ks = 0; ks < 4; ks++) {
                const int kk = ks * 8;
                unsigned ah0, ah1, ah2, ah3, al0, al1, al2, al3;
                {
                    const uint32_t ao = (uint32_t)((wM * 16 * KSU + kk + aLdK) * 4);
                    ldsm4(ah0, ah1, ah2, ah3, sQh + ao);
                    ldsm4(al0, al1, al2, al3, sQl + ao);
                }
                unsigned bf[7][2];
                #pragma unroll
                for (int p = 0; p < 3; p++) {
                    const uint32_t bo = (uint32_t)(((wN * 56 + p * 16) * KSU + kk + bLdK) * 4);
                    ldsm4(bf[2 * p][0], bf[2 * p][1], bf[2 * p + 1][0], bf[2 * p + 1][1], sK + bo);
                }
                {
                    const uint32_t bo = (uint32_t)(((wN * 56 + 48) * KSU + kk + bLdK2) * 4);
                    ldsm2(bf[6][0], bf[6][1], sK + bo);
                }
                #pragma unroll
                for (int t = 0; t < 7; t++) {
                    mma_f16(e[t][0], e[t][1], e[t][2], e[t][3],
                            ah0, ah1, ah2, ah3, bf[t][0], bf[t][1]);
                    mma_f16(e[t][0], e[t][1], e[t][2], e[t][3],
                            al0, al1, al2, al3, bf[t][0], bf[t][1]);
                }
            }
            #pragma unroll
            for (int t = 0; t < 7; t++) {
                const int col = wN * 56 + t * 8 + 2 * c;
                const int row = wM * 16 + g;
                *(float2*)(E + row * EPS + col)       = make_float2(e[t][0], e[t][1]);
                *(float2*)(E + (row + 8) * EPS + col) = make_float2(e[t][2], e[t][3]);
            }
        }
        __syncthreads();

        // ---- softmax rows (warp w owns rows 4w..4w+3); P (unnormalized)
        //      overwrites E; inv[row] saved for epilogue scaling ----
        {
            #pragma unroll
            for (int rr = 0; rr < 4; rr++) {
                const int row = warp * 4 + rr;
                const float* er = E + row * EPS;
                float e0[4], e1[4];
                float mx = -1e30f;
                int cnt = 0;
                for (int p2 = lane; p2 < 112; p2 += 32, cnt++) {
                    float2 ev = *(const float2*)(er + 2 * p2);
                    e0[cnt] = (2 * p2     < SEQ) ? ev.x : -1e30f;
                    e1[cnt] = (2 * p2 + 1 < SEQ) ? ev.y : -1e30f;
                    mx = fmaxf(mx, fmaxf(e0[cnt], e1[cnt]));
                }
                #pragma unroll
                for (int o = 16; o > 0; o >>= 1)
                    mx = fmaxf(mx, __shfl_xor_sync(0xffffffffu, mx, o));
                float sum = 0.f;
                #pragma unroll
                for (int i = 0; i < 4; i++) {
                    if (i < cnt) {
                        e0[i] = __expf(e0[i] - mx);
                        e1[i] = __expf(e1[i] - mx);
                        sum += e0[i] + e1[i];
                    }
                }
                #pragma unroll
                for (int o = 16; o > 0; o >>= 1)
                    sum += __shfl_xor_sync(0xffffffffu, sum, o);
                if (lane == 0)
                    Inv[row] = 1.0f / (sum * 27.712812921102035f);   // sqrt(768)
                // E reads done (shfl reductions are warp-synchronous) -> overwrite.
                cnt = 0;
                for (int p2 = lane; p2 < 112; p2 += 32, cnt++) {
                    float p0 = e0[cnt];
                    float p1 = e1[cnt];
                    float h0 = __half2float(__float2half_rn(p0));
                    float h1 = __half2float(__float2half_rn(p1));
                    Pu[row * EPS + p2]         = pack_h2(p0, p1);
                    Pu[row * EPS + PLOFF + p2] = pack_h2(p0 - h0, p1 - h1);
                }
            }
        }
        __syncthreads();

        // ---- O = P @ V : warp tile 16 rows x 16 cols ----
        {
            float o[2][4];
            #pragma unroll
            for (int t = 0; t < 2; t++)
                #pragma unroll
                for (int r = 0; r < 4; r++) o[t][r] = 0.f;

            #pragma unroll 2
            for (int ks = 0; ks < 14; ks++) {
                const int kk = ks * 8;
                unsigned ah0, ah1, ah2, ah3, al0, al1, al2, al3;
                {
                    const uint32_t ao = (uint32_t)((wM * 16 * EPS + kk + aLdP) * 4);
                    ldsm4(ah0, ah1, ah2, ah3, sEP + ao);
                    ldsm4(al0, al1, al2, al3, sEP + ao + PLOFF * 4);
                }
                unsigned bf[2][2];
                {
                    const uint32_t bo = (uint32_t)((wN * 16 * VSU + kk + bLdV) * 4);
                    ldsm4(bf[0][0], bf[0][1], bf[1][0], bf[1][1], sVt + bo);
                }
                #pragma unroll
                for (int t = 0; t < 2; t++) {
                    mma_f16(o[t][0], o[t][1], o[t][2], o[t][3],
                            ah0, ah1, ah2, ah3, bf[t][0], bf[t][1]);
                    mma_f16(o[t][0], o[t][1], o[t][2], o[t][3],
                            al0, al1, al2, al3, bf[t][0], bf[t][1]);
                }
            }
            const float inv0 = Inv[wM * 16 + g];
            const float inv1 = Inv[wM * 16 + 8 + g];
            #pragma unroll
            for (int t = 0; t < 2; t++) {
                const int col = wN * 16 + t * 8 + 2 * c;
                const int rg0 = rbase + wM * 16 + g;
                const int rg1 = rg0 + 8;
                if (rg0 < SEQ) {
                    float v0 = o[t][0] * inv0, v1 = o[t][1] * inv0;
                    float h0 = __half2float(__float2half_rn(v0));
                    float h1 = __half2float(__float2half_rn(v1));
                    AOh[(rg0 * HD + col) >> 1] = pack_h2(v0, v1);
                    AOl[(rg0 * HD + col) >> 1] = pack_h2(v0 - h0, v1 - h1);
                }
                if (rg1 < SEQ) {
                    float v0 = o[t][2] * inv1, v1 = o[t][3] * inv1;
                    float h0 = __half2float(__float2half_rn(v0));
                    float h1 = __half2float(__float2half_rn(v1));
                    AOh[(rg1 * HD + col) >> 1] = pack_h2(v0, v1);
                    AOl[(rg1 * HD + col) >> 1] = pack_h2(v0 - h0, v1 - h1);
                }
            }
        }
        __syncthreads();
    }
}

// ---------------------------------------------------------------------------
// Launch
// ---------------------------------------------------------------------------
extern "C" void kernel_launch(void* const* d_in, const int* in_sizes, int n_in,
                              void* d_out, int out_size)
{
    const float* x  = (const float*)d_in[0];
    const float* Wq = (const float*)d_in[1];
    const float* bq = (const float*)d_in[2];
    const float* Wk = (const float*)d_in[3];
    const float* bk = (const float*)d_in[4];
    const float* Wv = (const float*)d_in[5];
    const float* bv = (const float*)d_in[6];
    const float* Wp = (const float*)d_in[7];
    const float* bp = (const float*)d_in[8];
    float* out = (float*)d_out;

    cudaFuncSetAttribute(qkv_gemm_kernel,
                         cudaFuncAttributeMaxDynamicSharedMemorySize,
                         GEMM_SMEM_BYTES);
    cudaFuncSetAttribute(proj_gemm_kernel,
                         cudaFuncAttributeMaxDynamicSharedMemorySize,
                         GEMM_SMEM_BYTES);
    cudaFuncSetAttribute(attn_kernel,
                         cudaFuncAttributeMaxDynamicSharedMemorySize,
                         ATTN_SMEM_BYTES);

    const int n4x = MROWS * EDIM / 4;
    const int n4w = EDIM * EDIM / 4;
    split_x_kernel<<<(n4x + 255) / 256, 256>>>(x, n4x);
    dim3 gridW((n4w + 255) / 256, 1, 4);
    conv_w_kernel<<<gridW, 256>>>(Wq, Wk, Wv, Wp, n4w);

    dim3 gridQKV(EDIM / 128, (MROWS + 127) / 128, 3);   // (6, 99, 3)
    qkv_gemm_kernel<<<gridQKV, 256, GEMM_SMEM_BYTES>>>(bq, bk, bv);

    attn_kernel<<<BATCH * NH, 512, ATTN_SMEM_BYTES>>>();

    dim3 gridP(EDIM / 128, (MROWS + 127) / 128, 1);     // (6, 99)
    proj_gemm_kernel<<<gridP, 256, GEMM_SMEM_BYTES>>>(bp, out);
}

// round 12
// speedup vs baseline: 1.0622x; 1.0622x over previous
#include <cuda_runtime.h>
#include <cuda_fp16.h>
#include <cstdint>

// Problem constants
#define BATCH 64
#define SEQ   197
#define EDIM  768
#define NH    12
#define HD    64
#define MROWS (BATCH * SEQ)          // 12608
#define PERB  (SEQ * EDIM)
#define PERH  (SEQ * HD)

// fp16 operands. A-side (x, Q, AO) split hi+lo (~22 mantissa bits combined);
// B-side (W, K, V) rounded once to fp16.
__device__ __align__(16) __half g_x_hi[MROWS * EDIM];
__device__ __align__(16) __half g_x_lo[MROWS * EDIM];
__device__ __align__(16) __half g_w[4][EDIM * EDIM];     // q,k,v,p (single)
__device__ __align__(16) __half g_q_hi[MROWS * EDIM];
__device__ __align__(16) __half g_q_lo[MROWS * EDIM];
__device__ __align__(16) __half g_k[MROWS * EDIM];       // single
__device__ __align__(16) __half g_v[MROWS * EDIM];       // single
__device__ __align__(16) __half g_ao_hi[MROWS * EDIM];
__device__ __align__(16) __half g_ao_lo[MROWS * EDIM];

// ---------------------------------------------------------------------------
// mma / ldmatrix / cp.async helpers
// ---------------------------------------------------------------------------
__device__ __forceinline__ void mma_f16(
    float& d0, float& d1, float& d2, float& d3,
    unsigned a0, unsigned a1, unsigned a2, unsigned a3,
    unsigned b0, unsigned b1)
{
    asm volatile(
        "mma.sync.aligned.m16n8k16.row.col.f32.f16.f16.f32 "
        "{%0,%1,%2,%3}, {%4,%5,%6,%7}, {%8,%9}, {%0,%1,%2,%3};\n"
        : "+f"(d0), "+f"(d1), "+f"(d2), "+f"(d3)
        : "r"(a0), "r"(a1), "r"(a2), "r"(a3), "r"(b0), "r"(b1));
}

__device__ __forceinline__ void ldsm4(unsigned& r0, unsigned& r1,
                                      unsigned& r2, unsigned& r3, uint32_t addr)
{
    asm volatile("ldmatrix.sync.aligned.m8n8.x4.shared.b16 {%0,%1,%2,%3}, [%4];"
                 : "=r"(r0), "=r"(r1), "=r"(r2), "=r"(r3) : "r"(addr));
}

__device__ __forceinline__ void ldsm2(unsigned& r0, unsigned& r1, uint32_t addr)
{
    asm volatile("ldmatrix.sync.aligned.m8n8.x2.shared.b16 {%0,%1}, [%2];"
                 : "=r"(r0), "=r"(r1) : "r"(addr));
}

__device__ __forceinline__ void cp_async16(uint32_t dst, const void* src, int srcSz)
{
    asm volatile("cp.async.cg.shared.global [%0], [%1], 16, %2;"
                 :: "r"(dst), "l"(src), "r"(srcSz) : "memory");
}
#define CP_COMMIT() asm volatile("cp.async.commit_group;" ::: "memory")
#define CP_WAIT0()  asm volatile("cp.async.wait_group 0;" ::: "memory")

__device__ __forceinline__ unsigned prmt(unsigned a, unsigned b, unsigned sel) {
    unsigned r;
    asm("prmt.b32 %0, %1, %2, %3;" : "=r"(r) : "r"(a), "r"(b), "r"(sel));
    return r;
}

__device__ __forceinline__ unsigned pack_h2(float a, float b) {
    __half2 h = __floats2half2_rn(a, b);
    return *reinterpret_cast<unsigned*>(&h);
}

// ---------------------------------------------------------------------------
// Conversion kernels
// ---------------------------------------------------------------------------
__global__ void split_x_kernel(const float* __restrict__ x, int n4)
{
    int i = blockIdx.x * blockDim.x + threadIdx.x;
    if (i >= n4) return;
    float4 v = ((const float4*)x)[i];
    float h0 = __half2float(__float2half_rn(v.x));
    float h1 = __half2float(__float2half_rn(v.y));
    float h2 = __half2float(__float2half_rn(v.z));
    float h3 = __half2float(__float2half_rn(v.w));
    uint2 ph, pl;
    ph.x = pack_h2(v.x, v.y);
    ph.y = pack_h2(v.z, v.w);
    pl.x = pack_h2(v.x - h0, v.y - h1);
    pl.y = pack_h2(v.z - h2, v.w - h3);
    ((uint2*)g_x_hi)[i] = ph;
    ((uint2*)g_x_lo)[i] = pl;
}

__global__ void conv_w_kernel(const float* __restrict__ Wq,
                              const float* __restrict__ Wk,
                              const float* __restrict__ Wv,
                              const float* __restrict__ Wp, int n4)
{
    const float* src;
    const int z = blockIdx.z;
    if (z == 0) src = Wq; else if (z == 1) src = Wk;
    else if (z == 2) src = Wv; else src = Wp;
    int i = blockIdx.x * blockDim.x + threadIdx.x;
    if (i >= n4) return;
    float4 v = ((const float4*)src)[i];
    uint2 p;
    p.x = pack_h2(v.x, v.y);
    p.y = pack_h2(v.z, v.w);
    ((uint2*)g_w[z])[i] = p;
}

// ---------------------------------------------------------------------------
// fp16-2x NT GEMM: C[M,N] = (Ahi+Alo)[M,K] @ B[N,K]^T + bias
// BM=BN=128, BK=32, warp tile 64x32, ldmatrix + cp.async double-buffered.
// OUT_MODE: 0 = fp32 C; 1 = split f16 hi/lo; 2 = single f16.
// ---------------------------------------------------------------------------
#define RS 20                       // uint stride per smem row
#define ST_UINTS (128 * RS)
#define GEMM_SMEM_BYTES (6 * ST_UINTS * 4)    // 2 stages x 3 tiles = 61440 B

template <int OUT_MODE>
__device__ __forceinline__ void gemm_f16_body(
    const __half* __restrict__ Ahi, const __half* __restrict__ Alo,
    const __half* __restrict__ B,
    const float* __restrict__ bias,
    float* __restrict__ C,
    __half* __restrict__ Chi, __half* __restrict__ Clo)
{
    extern __shared__ unsigned smem_u[];

    const int tid  = threadIdx.x;
    const int warp = tid >> 5;
    const int lane = tid & 31;
    const int g    = lane >> 2;
    const int c    = lane & 3;
    const int warpM = warp & 1;
    const int warpN = warp >> 1;

    const int bm = blockIdx.y * 128;
    const int bn = blockIdx.x * 128;

    const int ldRow = tid >> 1;
    const int half_ = tid & 1;
    const int aRow  = bm + ldRow;
    const bool aValid = (aRow < MROWS);
    const int aSz = aValid ? 16 : 0;
    const size_t aOff = (size_t)(aValid ? aRow : 0) * EDIM + half_ * 16;
    const size_t bOff = (size_t)(bn + ldRow) * EDIM + half_ * 16;
    const int sBase = ldRow * RS + half_ * 8;

    const uint32_t smBase = (uint32_t)__cvta_generic_to_shared(smem_u);
    const int aLd = ((lane & 7) + 8 * ((lane >> 3) & 1)) * RS + 4 * (lane >> 4);
    const int bLd = ((lane & 7) + 8 * (lane >> 4)) * RS + 4 * ((lane >> 3) & 1);

    float acc[4][4][4];
    #pragma unroll
    for (int mt = 0; mt < 4; mt++)
        #pragma unroll
        for (int nt = 0; nt < 4; nt++)
            #pragma unroll
            for (int r = 0; r < 4; r++)
                acc[mt][nt][r] = 0.0f;

    auto issue = [&](int ch, int stage) {
        const size_t k0 = (size_t)ch * 32;
        const uint32_t st = smBase + (uint32_t)(stage * 3 * ST_UINTS) * 4;
        #pragma unroll
        for (int u = 0; u < 2; u++) {
            cp_async16(st + (uint32_t)(sBase + u * 4) * 4,                Ahi + aOff + k0 + u * 8, aSz);
            cp_async16(st + (uint32_t)(ST_UINTS + sBase + u * 4) * 4,     Alo + aOff + k0 + u * 8, aSz);
            cp_async16(st + (uint32_t)(2 * ST_UINTS + sBase + u * 4) * 4, B + bOff + k0 + u * 8, 16);
        }
        CP_COMMIT();
    };

    issue(0, 0);

    const int nCh = EDIM / 32;   // 24
    for (int ch = 0; ch < nCh; ch++) {
        const int stage = ch & 1;
        CP_WAIT0();
        __syncthreads();
        if (ch + 1 < nCh) issue(ch + 1, stage ^ 1);

        const uint32_t sAh = smBase + (uint32_t)(stage * 3 * ST_UINTS) * 4;
        const uint32_t sAl = sAh + ST_UINTS * 4;
        const uint32_t sB  = sAl + ST_UINTS * 4;

        #pragma unroll
        for (int ks = 0; ks < 2; ks++) {
            const int kk = ks * 8;
            unsigned ah[4][4], al[4][4], bf[4][2];
            #pragma unroll
            for (int mt = 0; mt < 4; mt++) {
                const uint32_t ao = (uint32_t)(((warpM * 64 + mt * 16) * RS + kk + aLd) * 4);
                ldsm4(ah[mt][0], ah[mt][1], ah[mt][2], ah[mt][3], sAh + ao);
                ldsm4(al[mt][0], al[mt][1], al[mt][2], al[mt][3], sAl + ao);
            }
            #pragma unroll
            for (int p = 0; p < 2; p++) {
                const uint32_t bo = (uint32_t)(((warpN * 32 + p * 16) * RS + kk + bLd) * 4);
                ldsm4(bf[2 * p][0], bf[2 * p][1], bf[2 * p + 1][0], bf[2 * p + 1][1], sB + bo);
            }
            #pragma unroll
            for (int mt = 0; mt < 4; mt++)
                #pragma unroll
                for (int nt = 0; nt < 4; nt++) {
                    float* d = acc[mt][nt];
                    mma_f16(d[0], d[1], d[2], d[3],
                            ah[mt][0], ah[mt][1], ah[mt][2], ah[mt][3],
                            bf[nt][0], bf[nt][1]);
                    mma_f16(d[0], d[1], d[2], d[3],
                            al[mt][0], al[mt][1], al[mt][2], al[mt][3],
                            bf[nt][0], bf[nt][1]);
                }
        }
        __syncthreads();
    }

    // epilogue
    #pragma unroll
    for (int mt = 0; mt < 4; mt++) {
        const int row0 = bm + warpM * 64 + mt * 16 + g;
        const int row1 = row0 + 8;
        #pragma unroll
        for (int nt = 0; nt < 4; nt++) {
            const int col = bn + warpN * 32 + nt * 8 + 2 * c;
            const float b0 = bias[col];
            const float b1 = bias[col + 1];
            float v00 = acc[mt][nt][0] + b0, v01 = acc[mt][nt][1] + b1;
            float v10 = acc[mt][nt][2] + b0, v11 = acc[mt][nt][3] + b1;
            if (OUT_MODE == 1) {
                if (row0 < MROWS) {
                    size_t ui = ((size_t)row0 * EDIM + col) >> 1;
                    float h0 = __half2float(__float2half_rn(v00));
                    float h1 = __half2float(__float2half_rn(v01));
                    ((unsigned*)Chi)[ui] = pack_h2(v00, v01);
                    ((unsigned*)Clo)[ui] = pack_h2(v00 - h0, v01 - h1);
                }
                if (row1 < MROWS) {
                    size_t ui = ((size_t)row1 * EDIM + col) >> 1;
                    float h0 = __half2float(__float2half_rn(v10));
                    float h1 = __half2float(__float2half_rn(v11));
                    ((unsigned*)Chi)[ui] = pack_h2(v10, v11);
                    ((unsigned*)Clo)[ui] = pack_h2(v10 - h0, v11 - h1);
                }
            } else if (OUT_MODE == 2) {
                if (row0 < MROWS)
                    ((unsigned*)Chi)[((size_t)row0 * EDIM + col) >> 1] = pack_h2(v00, v01);
                if (row1 < MROWS)
                    ((unsigned*)Chi)[((size_t)row1 * EDIM + col) >> 1] = pack_h2(v10, v11);
            } else {
                if (row0 < MROWS)
                    *(float2*)(C + (size_t)row0 * EDIM + col) = make_float2(v00, v01);
                if (row1 < MROWS)
                    *(float2*)(C + (size_t)row1 * EDIM + col) = make_float2(v10, v11);
            }
        }
    }
}

__global__ __launch_bounds__(256, 2) void qkv_gemm_kernel(
    const float* __restrict__ bq, const float* __restrict__ bk,
    const float* __restrict__ bv)
{
    if (blockIdx.z == 0)
        gemm_f16_body<1>(g_x_hi, g_x_lo, g_w[0], bq, nullptr, g_q_hi, g_q_lo);
    else if (blockIdx.z == 1)
        gemm_f16_body<2>(g_x_hi, g_x_lo, g_w[1], bk, nullptr, g_k, nullptr);
    else
        gemm_f16_body<2>(g_x_hi, g_x_lo, g_w[2], bv, nullptr, g_v, nullptr);
}

__global__ __launch_bounds__(256, 2) void proj_gemm_kernel(
    const float* __restrict__ bp, float* __restrict__ out)
{
    gemm_f16_body<0>(g_ao_hi, g_ao_lo, g_w[3], bp, out, nullptr, nullptr);
}

// ---------------------------------------------------------------------------
// Attention: fp16-2x mma + ldmatrix, 256 threads, 32-row stripes (7/head),
// smem 101.5 KB -> 2 CTAs/SM: independent CTAs overlap mma and softmax
// phases on the same SM. Q split hi/lo; K, V single fp16. P stored
// UNNORMALIZED split hi/lo (exact); 1/(sum*sqrt(768)) applied at O epilogue.
// ---------------------------------------------------------------------------
#define SP   224
#define KSU  36          // uint stride, K/Q rows
#define VSU  116         // uint stride, Vt rows
#define EPS  236         // word stride, E rows (fp32) / P rows (uints)
#define PLOFF 120        // Pl offset within an E/P row (uints)

#define SM_K    0
#define SM_VT   (SM_K + SP * KSU)                 // 8064
#define SM_QH   (SM_VT + 64 * VSU)                // 15488
#define SM_QL   (SM_QH + 32 * KSU)                // 16640
#define SM_INV  (SM_QL + 32 * KSU)                // 17792
#define SM_EP   (SM_INV + 32)                     // 17824
#define ATTN_SMEM_WORDS (SM_EP + 32 * EPS)        // 25376
#define ATTN_SMEM_BYTES (ATTN_SMEM_WORDS * 4)     // 101504 -> 2 CTAs/SM

__global__ __launch_bounds__(256, 2) void attn_kernel()
{
    extern __shared__ unsigned smw[];
    unsigned* Ks  = smw + SM_K;
    unsigned* Vt  = smw + SM_VT;
    unsigned* Qh  = smw + SM_QH;
    unsigned* Ql  = smw + SM_QL;
    float*    Inv = (float*)(smw + SM_INV);
    float*    E   = (float*)(smw + SM_EP);
    unsigned* Pu  = smw + SM_EP;     // P overlays E

    const int bh = blockIdx.x;
    const int b = bh / NH;
    const int h = bh % NH;
    const size_t base = (size_t)b * PERB + (size_t)h * PERH;

    const unsigned* Qgh = (const unsigned*)g_q_hi + (base >> 1);
    const unsigned* Qgl = (const unsigned*)g_q_lo + (base >> 1);
    const unsigned* Kg  = (const unsigned*)g_k + (base >> 1);
    const unsigned* Vg  = (const unsigned*)g_v + (base >> 1);
    unsigned* AOh = (unsigned*)g_ao_hi + (base >> 1);
    unsigned* AOl = (unsigned*)g_ao_lo + (base >> 1);

    const int tid  = threadIdx.x;
    const int warp = tid >> 5;      // 0..7
    const int lane = tid & 31;
    const int g    = lane >> 2;
    const int c    = lane & 3;
    const int wM   = warp & 1;      // 2 M-tiles of 16 rows
    const int wN   = warp >> 1;     // 4 N-groups

    const uint32_t smBase = (uint32_t)__cvta_generic_to_shared(smw);
    const uint32_t sK  = smBase + SM_K  * 4;
    const uint32_t sVt = smBase + SM_VT * 4;
    const uint32_t sQh = smBase + SM_QH * 4;
    const uint32_t sQl = smBase + SM_QL * 4;
    const uint32_t sEP = smBase + SM_EP * 4;

    const int aLdK = ((lane & 7) + 8 * ((lane >> 3) & 1)) * KSU + 4 * (lane >> 4);
    const int bLdK = ((lane & 7) + 8 * (lane >> 4)) * KSU + 4 * ((lane >> 3) & 1);
    const int bLdK2 = (lane & 7) * KSU + 4 * ((lane >> 3) & 1);
    const int aLdP = ((lane & 7) + 8 * ((lane >> 3) & 1)) * EPS + 4 * (lane >> 4);
    const int bLdV = ((lane & 7) + 8 * (lane >> 4)) * VSU + 4 * ((lane >> 3) & 1);

    // zero K + Vt regions (pad rows/cols must be 0 so PV sees p*0, not NaN)
    for (int i = tid; i < (SP * KSU + 64 * VSU) / 4; i += 256)
        ((uint4*)smw)[i] = make_uint4(0u, 0u, 0u, 0u);
    __syncthreads();

    // K fill (197 rows x 8 uint4)
    for (int t = tid; t < 197 * 8; t += 256) {
        int row = t >> 3, chk = t & 7;
        *(uint4*)(Ks + row * KSU + chk * 4) = *(const uint4*)(Kg + row * 32 + chk * 4);
    }
    // Vt fill (transpose + repack along j): 99 j-pairs x 8 d-chunks
    for (int t = tid; t < 99 * 8; t += 256) {
        int j2 = t >> 3, dch = t & 7;
        int j0 = 2 * j2;
        uint4 av = *(const uint4*)(Vg + j0 * 32 + dch * 4);
        uint4 bv = make_uint4(0u, 0u, 0u, 0u);
        if (j0 + 1 < SEQ)
            bv = *(const uint4*)(Vg + (j0 + 1) * 32 + dch * 4);
        const unsigned* ap = &av.x;
        const unsigned* bp = &bv.x;
        #pragma unroll
        for (int i = 0; i < 4; i++) {
            int d = dch * 8 + 2 * i;
            Vt[(d    ) * VSU + j2] = prmt(ap[i], bp[i], 0x5410);
            Vt[(d + 1) * VSU + j2] = prmt(ap[i], bp[i], 0x7632);
        }
    }
    __syncthreads();

    for (int stripe = 0; stripe < 7; stripe++) {
        const int rbase = stripe * 32;

        // load Q stripe: 32 rows x 8 chunks, 256 threads -> 1 each
        {
            int row = tid >> 3, chk = tid & 7;
            int rg = rbase + row;
            uint4 vh = make_uint4(0u, 0u, 0u, 0u), vl = vh;
            if (rg < SEQ) {
                vh = *(const uint4*)(Qgh + rg * 32 + chk * 4);
                vl = *(const uint4*)(Qgl + rg * 32 + chk * 4);
            }
            *(uint4*)(Qh + row * KSU + chk * 4) = vh;
            *(uint4*)(Ql + row * KSU + chk * 4) = vl;
        }
        __syncthreads();

        // ---- E = Q_stripe @ K^T : warp tile 16 rows x 56 cols ----
        {
            float e[7][4];
            #pragma unroll
            for (int t = 0; t < 7; t++)
                #pragma unroll
                for (int r = 0; r < 4; r++) e[t][r] = 0.f;

            #pragma unroll
            for (int ks = 0; ks < 4; ks++) {
                const int kk = ks * 8;
                unsigned ah0, ah1, ah2, ah3, al0, al1, al2, al3;
                {
                    const uint32_t ao = (uint32_t)((wM * 16 * KSU + kk + aLdK) * 4);
                    ldsm4(ah0, ah1, ah2, ah3, sQh + ao);
                    ldsm4(al0, al1, al2, al3, sQl + ao);
                }
                unsigned bf[7][2];
                #pragma unroll
                for (int p = 0; p < 3; p++) {
                    const uint32_t bo = (uint32_t)(((wN * 56 + p * 16) * KSU + kk + bLdK) * 4);
                    ldsm4(bf[2 * p][0], bf[2 * p][1], bf[2 * p + 1][0], bf[2 * p + 1][1], sK + bo);
                }
                {
                    const uint32_t bo = (uint32_t)(((wN * 56 + 48) * KSU + kk + bLdK2) * 4);
                    ldsm2(bf[6][0], bf[6][1], sK + bo);
                }
                #pragma unroll
                for (int t = 0; t < 7; t++) {
                    mma_f16(e[t][0], e[t][1], e[t][2], e[t][3],
                            ah0, ah1, ah2, ah3, bf[t][0], bf[t][1]);
                    mma_f16(e[t][0], e[t][1], e[t][2], e[t][3],
                            al0, al1, al2, al3, bf[t][0], bf[t][1]);
                }
            }
            #pragma unroll
            for (int t = 0; t < 7; t++) {
                const int col = wN * 56 + t * 8 + 2 * c;
                const int row = wM * 16 + g;
                *(float2*)(E + row * EPS + col)       = make_float2(e[t][0], e[t][1]);
                *(float2*)(E + (row + 8) * EPS + col) = make_float2(e[t][2], e[t][3]);
            }
        }
        __syncthreads();

        // ---- softmax rows (warp w owns rows 4w..4w+3); P (unnormalized)
        //      overwrites E; Inv[row] saved for epilogue scaling ----
        {
            #pragma unroll
            for (int rr = 0; rr < 4; rr++) {
                const int row = warp * 4 + rr;
                const float* er = E + row * EPS;
                float e0[4], e1[4];
                float mx = -1e30f;
                int cnt = 0;
                for (int p2 = lane; p2 < 112; p2 += 32, cnt++) {
                    float2 ev = *(const float2*)(er + 2 * p2);
                    e0[cnt] = (2 * p2     < SEQ) ? ev.x : -1e30f;
                    e1[cnt] = (2 * p2 + 1 < SEQ) ? ev.y : -1e30f;
                    mx = fmaxf(mx, fmaxf(e0[cnt], e1[cnt]));
                }
                #pragma unroll
                for (int o = 16; o > 0; o >>= 1)
                    mx = fmaxf(mx, __shfl_xor_sync(0xffffffffu, mx, o));
                float sum = 0.f;
                #pragma unroll
                for (int i = 0; i < 4; i++) {
                    if (i < cnt) {
                        e0[i] = __expf(e0[i] - mx);
                        e1[i] = __expf(e1[i] - mx);
                        sum += e0[i] + e1[i];
                    }
                }
                #pragma unroll
                for (int o = 16; o > 0; o >>= 1)
                    sum += __shfl_xor_sync(0xffffffffu, sum, o);
                if (lane == 0)
                    Inv[row] = 1.0f / (sum * 27.712812921102035f);   // sqrt(768)
                // E reads done (shfl reductions are warp-synchronous) -> overwrite.
                cnt = 0;
                for (int p2 = lane; p2 < 112; p2 += 32, cnt++) {
                    float p0 = e0[cnt];
                    float p1 = e1[cnt];
                    float h0 = __half2float(__float2half_rn(p0));
                    float h1 = __half2float(__float2half_rn(p1));
                    Pu[row * EPS + p2]         = pack_h2(p0, p1);
                    Pu[row * EPS + PLOFF + p2] = pack_h2(p0 - h0, p1 - h1);
                }
            }
        }
        __syncthreads();

        // ---- O = P @ V : warp tile 16 rows x 16 cols ----
        {
            float o[2][4];
            #pragma unroll
            for (int t = 0; t < 2; t++)
                #pragma unroll
                for (int r = 0; r < 4; r++) o[t][r] = 0.f;

            #pragma unroll 2
            for (int ks = 0; ks < 14; ks++) {
                const int kk = ks * 8;
                unsigned ah0, ah1, ah2, ah3, al0, al1, al2, al3;
                {
                    const uint32_t ao = (uint32_t)((wM * 16 * EPS + kk + aLdP) * 4);
                    ldsm4(ah0, ah1, ah2, ah3, sEP + ao);
                    ldsm4(al0, al1, al2, al3, sEP + ao + PLOFF * 4);
                }
                unsigned bf[2][2];
                {
                    const uint32_t bo = (uint32_t)((wN * 16 * VSU + kk + bLdV) * 4);
                    ldsm4(bf[0][0], bf[0][1], bf[1][0], bf[1][1], sVt + bo);
                }
                #pragma unroll
                for (int t = 0; t < 2; t++) {
                    mma_f16(o[t][0], o[t][1], o[t][2], o[t][3],
                            ah0, ah1, ah2, ah3, bf[t][0], bf[t][1]);
                    mma_f16(o[t][0], o[t][1], o[t][2], o[t][3],
                            al0, al1, al2, al3, bf[t][0], bf[t][1]);
                }
            }
            const float inv0 = Inv[wM * 16 + g];
            const float inv1 = Inv[wM * 16 + 8 + g];
            #pragma unroll
            for (int t = 0; t < 2; t++) {
                const int col = wN * 16 + t * 8 + 2 * c;
                const int rg0 = rbase + wM * 16 + g;
                const int rg1 = rg0 + 8;
                if (rg0 < SEQ) {
                    float v0 = o[t][0] * inv0, v1 = o[t][1] * inv0;
                    float h0 = __half2float(__float2half_rn(v0));
                    float h1 = __half2float(__float2half_rn(v1));
                    AOh[(rg0 * HD + col) >> 1] = pack_h2(v0, v1);
                    AOl[(rg0 * HD + col) >> 1] = pack_h2(v0 - h0, v1 - h1);
                }
                if (rg1 < SEQ) {
                    float v0 = o[t][2] * inv1, v1 = o[t][3] * inv1;
                    float h0 = __half2float(__float2half_rn(v0));
                    float h1 = __half2float(__float2half_rn(v1));
                    AOh[(rg1 * HD + col) >> 1] = pack_h2(v0, v1);
                    AOl[(rg1 * HD + col) >> 1] = pack_h2(v0 - h0, v1 - h1);
                }
            }
        }
        __syncthreads();
    }
}

// ---------------------------------------------------------------------------
// Launch
// ---------------------------------------------------------------------------
extern "C" void kernel_launch(void* const* d_in, const int* in_sizes, int n_in,
                              void* d_out, int out_size)
{
    const float* x  = (const float*)d_in[0];
    const float* Wq = (const float*)d_in[1];
    const float* bq = (const float*)d_in[2];
    const float* Wk = (const float*)d_in[3];
    const float* bk = (const float*)d_in[4];
    const float* Wv = (const float*)d_in[5];
    const float* bv = (const float*)d_in[6];
    const float* Wp = (const float*)d_in[7];
    const float* bp = (const float*)d_in[8];
    float* out = (float*)d_out;

    cudaFuncSetAttribute(qkv_gemm_kernel,
                         cudaFuncAttributeMaxDynamicSharedMemorySize,
                         GEMM_SMEM_BYTES);
    cudaFuncSetAttribute(proj_gemm_kernel,
                         cudaFuncAttributeMaxDynamicSharedMemorySize,
                         GEMM_SMEM_BYTES);
    cudaFuncSetAttribute(attn_kernel,
                         cudaFuncAttributeMaxDynamicSharedMemorySize,
                         ATTN_SMEM_BYTES);

    const int n4x = MROWS * EDIM / 4;
    const int n4w = EDIM * EDIM / 4;
    split_x_kernel<<<(n4x + 255) / 256, 256>>>(x, n4x);
    dim3 gridW((n4w + 255) / 256, 1, 4);
    conv_w_kernel<<<gridW, 256>>>(Wq, Wk, Wv, Wp, n4w);

    dim3 gridQKV(EDIM / 128, (MROWS + 127) / 128, 3);   // (6, 99, 3)
    qkv_gemm_kernel<<<gridQKV, 256, GEMM_SMEM_BYTES>>>(bq, bk, bv);

    attn_kernel<<<BATCH * NH, 256, ATTN_SMEM_BYTES>>>();

    dim3 gridP(EDIM / 128, (MROWS + 127) / 128, 1);     // (6, 99)
    proj_gemm_kernel<<<gridP, 256, GEMM_SMEM_BYTES>>>(bp, out);
}

// round 13
// speedup vs baseline: 2.4240x; 2.2821x over previous
#include <cuda_runtime.h>
#include <cuda_fp16.h>
#include <cstdint>

// Problem constants
#define BATCH 64
#define SEQ   197
#define EDIM  768
#define NH    12
#define HD    64
#define MROWS (BATCH * SEQ)          // 12608
#define PERB  (SEQ * EDIM)
#define PERH  (SEQ * HD)

// All operands single fp16 (error budget: measured 1.59e-4 with B-side-only
// rounding; both-sides predicts ~2-4e-4 vs 1e-3 threshold).
__device__ __align__(16) __half g_x[MROWS * EDIM];
__device__ __align__(16) __half g_w[4][EDIM * EDIM];     // q,k,v,p
__device__ __align__(16) __half g_q[MROWS * EDIM];
__device__ __align__(16) __half g_k[MROWS * EDIM];
__device__ __align__(16) __half g_v[MROWS * EDIM];
__device__ __align__(16) __half g_ao[MROWS * EDIM];

// ---------------------------------------------------------------------------
// mma / ldmatrix / cp.async helpers
// ---------------------------------------------------------------------------
__device__ __forceinline__ void mma_f16(
    float& d0, float& d1, float& d2, float& d3,
    unsigned a0, unsigned a1, unsigned a2, unsigned a3,
    unsigned b0, unsigned b1)
{
    asm volatile(
        "mma.sync.aligned.m16n8k16.row.col.f32.f16.f16.f32 "
        "{%0,%1,%2,%3}, {%4,%5,%6,%7}, {%8,%9}, {%0,%1,%2,%3};\n"
        : "+f"(d0), "+f"(d1), "+f"(d2), "+f"(d3)
        : "r"(a0), "r"(a1), "r"(a2), "r"(a3), "r"(b0), "r"(b1));
}

__device__ __forceinline__ void ldsm4(unsigned& r0, unsigned& r1,
                                      unsigned& r2, unsigned& r3, uint32_t addr)
{
    asm volatile("ldmatrix.sync.aligned.m8n8.x4.shared.b16 {%0,%1,%2,%3}, [%4];"
                 : "=r"(r0), "=r"(r1), "=r"(r2), "=r"(r3) : "r"(addr));
}

__device__ __forceinline__ void ldsm2(unsigned& r0, unsigned& r1, uint32_t addr)
{
    asm volatile("ldmatrix.sync.aligned.m8n8.x2.shared.b16 {%0,%1}, [%2];"
                 : "=r"(r0), "=r"(r1) : "r"(addr));
}

__device__ __forceinline__ void cp_async16(uint32_t dst, const void* src, int srcSz)
{
    asm volatile("cp.async.cg.shared.global [%0], [%1], 16, %2;"
                 :: "r"(dst), "l"(src), "r"(srcSz) : "memory");
}
#define CP_COMMIT() asm volatile("cp.async.commit_group;" ::: "memory")
#define CP_WAIT0()  asm volatile("cp.async.wait_group 0;" ::: "memory")

__device__ __forceinline__ unsigned prmt(unsigned a, unsigned b, unsigned sel) {
    unsigned r;
    asm("prmt.b32 %0, %1, %2, %3;" : "=r"(r) : "r"(a), "r"(b), "r"(sel));
    return r;
}

__device__ __forceinline__ unsigned pack_h2(float a, float b) {
    __half2 h = __floats2half2_rn(a, b);
    return *reinterpret_cast<unsigned*>(&h);
}

// ---------------------------------------------------------------------------
// Conversion kernels: fp32 -> fp16
// ---------------------------------------------------------------------------
__global__ void conv_x_kernel(const float* __restrict__ x, int n4)
{
    int i = blockIdx.x * blockDim.x + threadIdx.x;
    if (i >= n4) return;
    float4 v = ((const float4*)x)[i];
    uint2 p;
    p.x = pack_h2(v.x, v.y);
    p.y = pack_h2(v.z, v.w);
    ((uint2*)g_x)[i] = p;
}

__global__ void conv_w_kernel(const float* __restrict__ Wq,
                              const float* __restrict__ Wk,
                              const float* __restrict__ Wv,
                              const float* __restrict__ Wp, int n4)
{
    const float* src;
    const int z = blockIdx.z;
    if (z == 0) src = Wq; else if (z == 1) src = Wk;
    else if (z == 2) src = Wv; else src = Wp;
    int i = blockIdx.x * blockDim.x + threadIdx.x;
    if (i >= n4) return;
    float4 v = ((const float4*)src)[i];
    uint2 p;
    p.x = pack_h2(v.x, v.y);
    p.y = pack_h2(v.z, v.w);
    ((uint2*)g_w[z])[i] = p;
}

// ---------------------------------------------------------------------------
// fp16 single-term NT GEMM: C[M,N] = A[M,K] @ B[N,K]^T + bias
// BM=BN=128, BK=32, warp tile 64x32, ldmatrix + cp.async double-buffered.
// OUT_MODE: 0 = fp32 C; 2 = f16 C.
// ---------------------------------------------------------------------------
#define RS 20                       // uint stride per smem row
#define ST_UINTS (128 * RS)
#define GEMM_SMEM_BYTES (4 * ST_UINTS * 4)    // 2 stages x 2 tiles = 40960 B

template <int OUT_MODE>
__device__ __forceinline__ void gemm_f16_body(
    const __half* __restrict__ A,
    const __half* __restrict__ B,
    const float* __restrict__ bias,
    float* __restrict__ C,
    __half* __restrict__ Ch)
{
    extern __shared__ unsigned smem_u[];

    const int tid  = threadIdx.x;
    const int warp = tid >> 5;
    const int lane = tid & 31;
    const int g    = lane >> 2;
    const int c    = lane & 3;
    const int warpM = warp & 1;
    const int warpN = warp >> 1;

    const int bm = blockIdx.y * 128;
    const int bn = blockIdx.x * 128;

    const int ldRow = tid >> 1;
    const int half_ = tid & 1;
    const int aRow  = bm + ldRow;
    const bool aValid = (aRow < MROWS);
    const int aSz = aValid ? 16 : 0;
    const size_t aOff = (size_t)(aValid ? aRow : 0) * EDIM + half_ * 16;
    const size_t bOff = (size_t)(bn + ldRow) * EDIM + half_ * 16;
    const int sBase = ldRow * RS + half_ * 8;

    const uint32_t smBase = (uint32_t)__cvta_generic_to_shared(smem_u);
    const int aLd = ((lane & 7) + 8 * ((lane >> 3) & 1)) * RS + 4 * (lane >> 4);
    const int bLd = ((lane & 7) + 8 * (lane >> 4)) * RS + 4 * ((lane >> 3) & 1);

    float acc[4][4][4];
    #pragma unroll
    for (int mt = 0; mt < 4; mt++)
        #pragma unroll
        for (int nt = 0; nt < 4; nt++)
            #pragma unroll
            for (int r = 0; r < 4; r++)
                acc[mt][nt][r] = 0.0f;

    auto issue = [&](int ch, int stage) {
        const size_t k0 = (size_t)ch * 32;
        const uint32_t st = smBase + (uint32_t)(stage * 2 * ST_UINTS) * 4;
        #pragma unroll
        for (int u = 0; u < 2; u++) {
            cp_async16(st + (uint32_t)(sBase + u * 4) * 4,            A + aOff + k0 + u * 8, aSz);
            cp_async16(st + (uint32_t)(ST_UINTS + sBase + u * 4) * 4, B + bOff + k0 + u * 8, 16);
        }
        CP_COMMIT();
    };

    issue(0, 0);

    const int nCh = EDIM / 32;   // 24
    for (int ch = 0; ch < nCh; ch++) {
        const int stage = ch & 1;
        CP_WAIT0();
        __syncthreads();
        if (ch + 1 < nCh) issue(ch + 1, stage ^ 1);

        const uint32_t sA = smBase + (uint32_t)(stage * 2 * ST_UINTS) * 4;
        const uint32_t sB = sA + ST_UINTS * 4;

        #pragma unroll
        for (int ks = 0; ks < 2; ks++) {
            const int kk = ks * 8;
            unsigned af[4][4], bf[4][2];
            #pragma unroll
            for (int mt = 0; mt < 4; mt++) {
                const uint32_t ao = (uint32_t)(((warpM * 64 + mt * 16) * RS + kk + aLd) * 4);
                ldsm4(af[mt][0], af[mt][1], af[mt][2], af[mt][3], sA + ao);
            }
            #pragma unroll
            for (int p = 0; p < 2; p++) {
                const uint32_t bo = (uint32_t)(((warpN * 32 + p * 16) * RS + kk + bLd) * 4);
                ldsm4(bf[2 * p][0], bf[2 * p][1], bf[2 * p + 1][0], bf[2 * p + 1][1], sB + bo);
            }
            #pragma unroll
            for (int mt = 0; mt < 4; mt++)
                #pragma unroll
                for (int nt = 0; nt < 4; nt++)
                    mma_f16(acc[mt][nt][0], acc[mt][nt][1], acc[mt][nt][2], acc[mt][nt][3],
                            af[mt][0], af[mt][1], af[mt][2], af[mt][3],
                            bf[nt][0], bf[nt][1]);
        }
        __syncthreads();
    }

    // epilogue
    #pragma unroll
    for (int mt = 0; mt < 4; mt++) {
        const int row0 = bm + warpM * 64 + mt * 16 + g;
        const int row1 = row0 + 8;
        #pragma unroll
        for (int nt = 0; nt < 4; nt++) {
            const int col = bn + warpN * 32 + nt * 8 + 2 * c;
            const float b0 = bias[col];
            const float b1 = bias[col + 1];
            float v00 = acc[mt][nt][0] + b0, v01 = acc[mt][nt][1] + b1;
            float v10 = acc[mt][nt][2] + b0, v11 = acc[mt][nt][3] + b1;
            if (OUT_MODE == 2) {
                if (row0 < MROWS)
                    ((unsigned*)Ch)[((size_t)row0 * EDIM + col) >> 1] = pack_h2(v00, v01);
                if (row1 < MROWS)
                    ((unsigned*)Ch)[((size_t)row1 * EDIM + col) >> 1] = pack_h2(v10, v11);
            } else {
                if (row0 < MROWS)
                    *(float2*)(C + (size_t)row0 * EDIM + col) = make_float2(v00, v01);
                if (row1 < MROWS)
                    *(float2*)(C + (size_t)row1 * EDIM + col) = make_float2(v10, v11);
            }
        }
    }
}

__global__ __launch_bounds__(256, 2) void qkv_gemm_kernel(
    const float* __restrict__ bq, const float* __restrict__ bk,
    const float* __restrict__ bv)
{
    const __half* W;
    const float* bias;
    __half* Ch;
    if (blockIdx.z == 0)      { W = g_w[0]; bias = bq; Ch = g_q; }
    else if (blockIdx.z == 1) { W = g_w[1]; bias = bk; Ch = g_k; }
    else                      { W = g_w[2]; bias = bv; Ch = g_v; }
    gemm_f16_body<2>(g_x, W, bias, nullptr, Ch);
}

__global__ __launch_bounds__(256, 2) void proj_gemm_kernel(
    const float* __restrict__ bp, float* __restrict__ out)
{
    gemm_f16_body<0>(g_ao, g_w[3], bp, out, nullptr);
}

// ---------------------------------------------------------------------------
// Attention: fp16 single-term mma + ldmatrix, 256 threads, 32-row stripes
// (7/head), smem 96.9 KB -> 2 CTAs/SM. P stored UNNORMALIZED fp16;
// 1/(sum*sqrt(768)) applied at O epilogue via Inv[].
// ---------------------------------------------------------------------------
#define SP   224
#define KSU  36          // uint stride, K/Q rows
#define VSU  116         // uint stride, Vt rows
#define EPS  236         // word stride, E rows (fp32) / P rows (uints)

#define SM_K    0
#define SM_VT   (SM_K + SP * KSU)                 // 8064
#define SM_Q    (SM_VT + 64 * VSU)                // 15488
#define SM_INV  (SM_Q + 32 * KSU)                 // 16640
#define SM_EP   (SM_INV + 32)                     // 16672
#define ATTN_SMEM_WORDS (SM_EP + 32 * EPS)        // 24224
#define ATTN_SMEM_BYTES (ATTN_SMEM_WORDS * 4)     // 96896 -> 2 CTAs/SM

__global__ __launch_bounds__(256, 2) void attn_kernel()
{
    extern __shared__ unsigned smw[];
    unsigned* Ks  = smw + SM_K;
    unsigned* Vt  = smw + SM_VT;
    unsigned* Qs  = smw + SM_Q;
    float*    Inv = (float*)(smw + SM_INV);
    float*    E   = (float*)(smw + SM_EP);
    unsigned* Pu  = smw + SM_EP;     // P overlays E

    const int bh = blockIdx.x;
    const int b = bh / NH;
    const int h = bh % NH;
    const size_t base = (size_t)b * PERB + (size_t)h * PERH;

    const unsigned* Qg = (const unsigned*)g_q + (base >> 1);
    const unsigned* Kg = (const unsigned*)g_k + (base >> 1);
    const unsigned* Vg = (const unsigned*)g_v + (base >> 1);
    unsigned* AOg = (unsigned*)g_ao + (base >> 1);

    const int tid  = threadIdx.x;
    const int warp = tid >> 5;      // 0..7
    const int lane = tid & 31;
    const int g    = lane >> 2;
    const int c    = lane & 3;
    const int wM   = warp & 1;      // 2 M-tiles of 16 rows
    const int wN   = warp >> 1;     // 4 N-groups

    const uint32_t smBase = (uint32_t)__cvta_generic_to_shared(smw);
    const uint32_t sK  = smBase + SM_K  * 4;
    const uint32_t sVt = smBase + SM_VT * 4;
    const uint32_t sQ  = smBase + SM_Q  * 4;
    const uint32_t sEP = smBase + SM_EP * 4;

    const int aLdK = ((lane & 7) + 8 * ((lane >> 3) & 1)) * KSU + 4 * (lane >> 4);
    const int bLdK = ((lane & 7) + 8 * (lane >> 4)) * KSU + 4 * ((lane >> 3) & 1);
    const int bLdK2 = (lane & 7) * KSU + 4 * ((lane >> 3) & 1);
    const int aLdP = ((lane & 7) + 8 * ((lane >> 3) & 1)) * EPS + 4 * (lane >> 4);
    const int bLdV = ((lane & 7) + 8 * (lane >> 4)) * VSU + 4 * ((lane >> 3) & 1);

    // zero K + Vt regions (pad rows/cols must be 0 so PV sees p*0, not NaN)
    for (int i = tid; i < (SP * KSU + 64 * VSU) / 4; i += 256)
        ((uint4*)smw)[i] = make_uint4(0u, 0u, 0u, 0u);
    __syncthreads();

    // K fill (197 rows x 8 uint4)
    for (int t = tid; t < 197 * 8; t += 256) {
        int row = t >> 3, chk = t & 7;
        *(uint4*)(Ks + row * KSU + chk * 4) = *(const uint4*)(Kg + row * 32 + chk * 4);
    }
    // Vt fill (transpose + repack along j): 99 j-pairs x 8 d-chunks
    for (int t = tid; t < 99 * 8; t += 256) {
        int j2 = t >> 3, dch = t & 7;
        int j0 = 2 * j2;
        uint4 av = *(const uint4*)(Vg + j0 * 32 + dch * 4);
        uint4 bv = make_uint4(0u, 0u, 0u, 0u);
        if (j0 + 1 < SEQ)
            bv = *(const uint4*)(Vg + (j0 + 1) * 32 + dch * 4);
        const unsigned* ap = &av.x;
        const unsigned* bp = &bv.x;
        #pragma unroll
        for (int i = 0; i < 4; i++) {
            int d = dch * 8 + 2 * i;
            Vt[(d    ) * VSU + j2] = prmt(ap[i], bp[i], 0x5410);
            Vt[(d + 1) * VSU + j2] = prmt(ap[i], bp[i], 0x7632);
        }
    }
    __syncthreads();

    for (int stripe = 0; stripe < 7; stripe++) {
        const int rbase = stripe * 32;

        // load Q stripe: 32 rows x 8 chunks, 256 threads -> 1 each
        {
            int row = tid >> 3, chk = tid & 7;
            int rg = rbase + row;
            uint4 v = make_uint4(0u, 0u, 0u, 0u);
            if (rg < SEQ)
                v = *(const uint4*)(Qg + rg * 32 + chk * 4);
            *(uint4*)(Qs + row * KSU + chk * 4) = v;
        }
        __syncthreads();

        // ---- E = Q_stripe @ K^T : warp tile 16 rows x 56 cols ----
        {
            float e[7][4];
            #pragma unroll
            for (int t = 0; t < 7; t++)
                #pragma unroll
                for (int r = 0; r < 4; r++) e[t][r] = 0.f;

            #pragma unroll
            for (int ks = 0; ks < 4; ks++) {
                const int kk = ks * 8;
                unsigned a0, a1, a2, a3;
                {
                    const uint32_t ao = (uint32_t)((wM * 16 * KSU + kk + aLdK) * 4);
                    ldsm4(a0, a1, a2, a3, sQ + ao);
                }
                unsigned bf[7][2];
                #pragma unroll
                for (int p = 0; p < 3; p++) {
                    const uint32_t bo = (uint32_t)(((wN * 56 + p * 16) * KSU + kk + bLdK) * 4);
                    ldsm4(bf[2 * p][0], bf[2 * p][1], bf[2 * p + 1][0], bf[2 * p + 1][1], sK + bo);
                }
                {
                    const uint32_t bo = (uint32_t)(((wN * 56 + 48) * KSU + kk + bLdK2) * 4);
                    ldsm2(bf[6][0], bf[6][1], sK + bo);
                }
                #pragma unroll
                for (int t = 0; t < 7; t++)
                    mma_f16(e[t][0], e[t][1], e[t][2], e[t][3],
                            a0, a1, a2, a3, bf[t][0], bf[t][1]);
            }
            #pragma unroll
            for (int t = 0; t < 7; t++) {
                const int col = wN * 56 + t * 8 + 2 * c;
                const int row = wM * 16 + g;
                *(float2*)(E + row * EPS + col)       = make_float2(e[t][0], e[t][1]);
                *(float2*)(E + (row + 8) * EPS + col) = make_float2(e[t][2], e[t][3]);
            }
        }
        __syncthreads();

        // ---- softmax rows (warp w owns rows 4w..4w+3); P (unnormalized fp16)
        //      overwrites E; Inv[row] saved for epilogue scaling ----
        {
            #pragma unroll
            for (int rr = 0; rr < 4; rr++) {
                const int row = warp * 4 + rr;
                const float* er = E + row * EPS;
                float e0[4], e1[4];
                float mx = -1e30f;
                int cnt = 0;
                for (int p2 = lane; p2 < 112; p2 += 32, cnt++) {
                    float2 ev = *(const float2*)(er + 2 * p2);
                    e0[cnt] = (2 * p2     < SEQ) ? ev.x : -1e30f;
                    e1[cnt] = (2 * p2 + 1 < SEQ) ? ev.y : -1e30f;
                    mx = fmaxf(mx, fmaxf(e0[cnt], e1[cnt]));
                }
                #pragma unroll
                for (int o = 16; o > 0; o >>= 1)
                    mx = fmaxf(mx, __shfl_xor_sync(0xffffffffu, mx, o));
                float sum = 0.f;
                #pragma unroll
                for (int i = 0; i < 4; i++) {
                    if (i < cnt) {
                        e0[i] = __expf(e0[i] - mx);
                        e1[i] = __expf(e1[i] - mx);
                        sum += e0[i] + e1[i];
                    }
                }
                #pragma unroll
                for (int o = 16; o > 0; o >>= 1)
                    sum += __shfl_xor_sync(0xffffffffu, sum, o);
                if (lane == 0)
                    Inv[row] = 1.0f / (sum * 27.712812921102035f);   // sqrt(768)
                // E reads done (shfl reductions are warp-synchronous) -> overwrite.
                cnt = 0;
                for (int p2 = lane; p2 < 112; p2 += 32, cnt++)
                    Pu[row * EPS + p2] = pack_h2(e0[cnt], e1[cnt]);
            }
        }
        __syncthreads();

        // ---- O = P @ V : warp tile 16 rows x 16 cols ----
        {
            float o[2][4];
            #pragma unroll
            for (int t = 0; t < 2; t++)
                #pragma unroll
                for (int r = 0; r < 4; r++) o[t][r] = 0.f;

            #pragma unroll 2
            for (int ks = 0; ks < 14; ks++) {
                const int kk = ks * 8;
                unsigned a0, a1, a2, a3;
                {
                    const uint32_t ao = (uint32_t)((wM * 16 * EPS + kk + aLdP) * 4);
                    ldsm4(a0, a1, a2, a3, sEP + ao);
                }
                unsigned bf[2][2];
                {
                    const uint32_t bo = (uint32_t)((wN * 16 * VSU + kk + bLdV) * 4);
                    ldsm4(bf[0][0], bf[0][1], bf[1][0], bf[1][1], sVt + bo);
                }
                #pragma unroll
                for (int t = 0; t < 2; t++)
                    mma_f16(o[t][0], o[t][1], o[t][2], o[t][3],
                            a0, a1, a2, a3, bf[t][0], bf[t][1]);
            }
            const float inv0 = Inv[wM * 16 + g];
            const float inv1 = Inv[wM * 16 + 8 + g];
            #pragma unroll
            for (int t = 0; t < 2; t++) {
                const int col = wN * 16 + t * 8 + 2 * c;
                const int rg0 = rbase + wM * 16 + g;
                const int rg1 = rg0 + 8;
                if (rg0 < SEQ)
                    AOg[(rg0 * HD + col) >> 1] = pack_h2(o[t][0] * inv0, o[t][1] * inv0);
                if (rg1 < SEQ)
                    AOg[(rg1 * HD + col) >> 1] = pack_h2(o[t][2] * inv1, o[t][3] * inv1);
            }
        }
        __syncthreads();
    }
}

// ---------------------------------------------------------------------------
// Launch
// ---------------------------------------------------------------------------
extern "C" void kernel_launch(void* const* d_in, const int* in_sizes, int n_in,
                              void* d_out, int out_size)
{
    const float* x  = (const float*)d_in[0];
    const float* Wq = (const float*)d_in[1];
    const float* bq = (const float*)d_in[2];
    const float* Wk = (const float*)d_in[3];
    const float* bk = (const float*)d_in[4];
    const float* Wv = (const float*)d_in[5];
    const float* bv = (const float*)d_in[6];
    const float* Wp = (const float*)d_in[7];
    const float* bp = (const float*)d_in[8];
    float* out = (float*)d_out;

    cudaFuncSetAttribute(qkv_gemm_kernel,
                         cudaFuncAttributeMaxDynamicSharedMemorySize,
                         GEMM_SMEM_BYTES);
    cudaFuncSetAttribute(proj_gemm_kernel,
                         cudaFuncAttributeMaxDynamicSharedMemorySize,
                         GEMM_SMEM_BYTES);
    cudaFuncSetAttribute(attn_kernel,
                         cudaFuncAttributeMaxDynamicSharedMemorySize,
                         ATTN_SMEM_BYTES);

    const int n4x = MROWS * EDIM / 4;
    const int n4w = EDIM * EDIM / 4;
    conv_x_kernel<<<(n4x + 255) / 256, 256>>>(x, n4x);
    dim3 gridW((n4w + 255) / 256, 1, 4);
    conv_w_kernel<<<gridW, 256>>>(Wq, Wk, Wv, Wp, n4w);

    dim3 gridQKV(EDIM / 128, (MROWS + 127) / 128, 3);   // (6, 99, 3)
    qkv_gemm_kernel<<<gridQKV, 256, GEMM_SMEM_BYTES>>>(bq, bk, bv);

    attn_kernel<<<BATCH * NH, 256, ATTN_SMEM_BYTES>>>();

    dim3 gridP(EDIM / 128, (MROWS + 127) / 128, 1);     // (6, 99)
    proj_gemm_kernel<<<gridP, 256, GEMM_SMEM_BYTES>>>(bp, out);
}